// round 1
// baseline (speedup 1.0000x reference)
#include <cuda_runtime.h>

// Aggregator_9964324127508 — GB300 sm_103a
//
// Pipeline (all in default stream, graph-capturable, no allocations):
//   1. ent_init     : g_ent = 0.8*emb + 0.2*emb (matches reference rounding)
//   2. region_gemm  : g_ent[R0:R1] = 0.8*emb + 0.2*(RWM @ emb[R0:R1])
//   3. zero_all     : zero d_out (entity+user sums) and g_cnt
//   4. kg_agg       : per-edge gather ent[tail]*rel -> red.v4 into sums[head], count++
//   5. user_agg     : per-nnz val*ent[col] -> red.v4 into user sums[row]
//   6. finalize     : entity sums /= max(count,1)
//
// Output layout: d_out[0 .. N_ENT*C)            = entity_agg
//                d_out[N_ENT*C .. +N_USR*C)     = user_agg

#define N_ENT   100000
#define N_USR   50000
#define C       64
#define N_EDGES 1600000
#define NNZ     1000000
#define N_REL   32
#define R0      42033
#define RD      2597      // R1 - R0

__device__ float g_ent[N_ENT * C];   // blended entity embedding (~25.6 MB)
__device__ int   g_cnt[N_ENT];       // per-head edge counts

// ---------------------------------------------------------------------------
// 1. blend all rows: ent = 0.8*e + 0.2*e  (region rows overwritten later)
// ---------------------------------------------------------------------------
__global__ void ent_init(const float4* __restrict__ emb) {
    int i = blockIdx.x * blockDim.x + threadIdx.x;
    if (i < N_ENT * C / 4) {
        float4 e = emb[i];
        float4 r;
        r.x = e.x * 0.8f + e.x * 0.2f;
        r.y = e.y * 0.8f + e.y * 0.2f;
        r.z = e.z * 0.8f + e.z * 0.2f;
        r.w = e.w * 0.8f + e.w * 0.2f;
        reinterpret_cast<float4*>(g_ent)[i] = r;
    }
}

// ---------------------------------------------------------------------------
// 2. region GEMM:  out[r,c] = sum_k RWM[r,k] * emb[R0+k, c],  then blend.
//    M=2597, N=64, K=2597. Tile: 16 rows x 64 cols per block (163 blocks,
//    full-chip), K tiled by 32 in shared memory.
// ---------------------------------------------------------------------------
#define GMT 16   // rows per block
#define GKT 32   // k per tile

__global__ __launch_bounds__(256, 4) void region_gemm(
        const float* __restrict__ emb, const float* __restrict__ rwm) {
    __shared__ float As[GMT][GKT + 1];   // RWM tile, +1 pad
    __shared__ float Bs[GKT][C];         // emb tile (rows 256B, float4-aligned)

    const int tid = threadIdx.x;
    const int ty  = tid >> 4;            // 0..15 : row within tile
    const int tx  = tid & 15;            // 0..15 : col group (4 cols)
    const int row0 = blockIdx.x * GMT;

    float4 acc = make_float4(0.f, 0.f, 0.f, 0.f);

    for (int k0 = 0; k0 < RD; k0 += GKT) {
        // load A tile: 16x32 = 512 elems, coalesced along k
        for (int t = tid; t < GMT * GKT; t += 256) {
            int r = t >> 5, k = t & 31;
            int gr = row0 + r, gk = k0 + k;
            As[r][k] = (gr < RD && gk < RD) ? rwm[gr * RD + gk] : 0.f;
        }
        // load B tile: 32x64 = 2048 elems, coalesced along c
        for (int t = tid; t < GKT * C; t += 256) {
            int k = t >> 6, c = t & 63;
            int gk = k0 + k;
            Bs[k][c] = (gk < RD) ? emb[(R0 + gk) * C + c] : 0.f;
        }
        __syncthreads();

        #pragma unroll
        for (int kk = 0; kk < GKT; kk++) {
            float a  = As[ty][kk];
            float4 b = *reinterpret_cast<const float4*>(&Bs[kk][tx * 4]);
            acc.x += a * b.x;
            acc.y += a * b.y;
            acc.z += a * b.z;
            acc.w += a * b.w;
        }
        __syncthreads();
    }

    int row = row0 + ty;
    if (row < RD) {
        int base = (R0 + row) * C + tx * 4;
        float4 e = *reinterpret_cast<const float4*>(&emb[base]);
        float4 o;
        o.x = e.x * 0.8f + acc.x * 0.2f;
        o.y = e.y * 0.8f + acc.y * 0.2f;
        o.z = e.z * 0.8f + acc.z * 0.2f;
        o.w = e.w * 0.8f + acc.w * 0.2f;
        *reinterpret_cast<float4*>(&g_ent[base]) = o;
    }
}

// ---------------------------------------------------------------------------
// 3. zero output sums and counts (d_out is poisoned by the harness)
// ---------------------------------------------------------------------------
__global__ void zero_all(float4* __restrict__ out) {
    int i = blockIdx.x * blockDim.x + threadIdx.x;
    const float4 z = make_float4(0.f, 0.f, 0.f, 0.f);
    if (i < (N_ENT + N_USR) * C / 4) out[i] = z;
    if (i < N_ENT / 4) {
        reinterpret_cast<int4*>(g_cnt)[i] = make_int4(0, 0, 0, 0);
    }
}

// ---------------------------------------------------------------------------
// 4. KG aggregate: 16 threads per edge, each handles 4 channels.
//    sums[head] += ent[tail] * weight[(etype-1) mod 32]   (red.global.v4)
// ---------------------------------------------------------------------------
__global__ __launch_bounds__(256, 8) void kg_agg(
        const int* __restrict__ eidx, const int* __restrict__ etype,
        const float* __restrict__ weight, float* __restrict__ out_ent) {
    long long t = (long long)blockIdx.x * blockDim.x + threadIdx.x;
    int e = (int)(t >> 4);
    if (e >= N_EDGES) return;
    int lane = (int)(t & 15);
    int c = lane * 4;

    int head = eidx[e];
    int tail = eidx[N_EDGES + e];
    int rt   = (etype[e] + (N_REL - 1)) & (N_REL - 1);   // (t-1) floor-mod 32

    float4 x = *reinterpret_cast<const float4*>(&g_ent[tail * C + c]);
    float4 w = *reinterpret_cast<const float4*>(&weight[rt * C + c]);
    float4 v;
    v.x = x.x * w.x; v.y = x.y * w.y; v.z = x.z * w.z; v.w = x.w * w.w;

    float* p = &out_ent[head * C + c];
    asm volatile("red.global.add.v4.f32 [%0], {%1, %2, %3, %4};"
                 :: "l"(p), "f"(v.x), "f"(v.y), "f"(v.z), "f"(v.w)
                 : "memory");
    if (lane == 0) atomicAdd(&g_cnt[head], 1);
}

// ---------------------------------------------------------------------------
// 5. user aggregate: 16 threads per nnz, 4 channels each.
//    user[row] += val * ent[col]
// ---------------------------------------------------------------------------
__global__ __launch_bounds__(256, 8) void user_agg(
        const int* __restrict__ rows, const int* __restrict__ cols,
        const float* __restrict__ vals, float* __restrict__ out_usr) {
    long long t = (long long)blockIdx.x * blockDim.x + threadIdx.x;
    int i = (int)(t >> 4);
    if (i >= NNZ) return;
    int lane = (int)(t & 15);
    int c = lane * 4;

    int r  = rows[i];
    int cl = cols[i];
    float val = vals[i];

    float4 x = *reinterpret_cast<const float4*>(&g_ent[cl * C + c]);
    float4 v;
    v.x = x.x * val; v.y = x.y * val; v.z = x.z * val; v.w = x.w * val;

    float* p = &out_usr[r * C + c];
    asm volatile("red.global.add.v4.f32 [%0], {%1, %2, %3, %4};"
                 :: "l"(p), "f"(v.x), "f"(v.y), "f"(v.z), "f"(v.w)
                 : "memory");
}

// ---------------------------------------------------------------------------
// 6. entity_agg = sums / max(count, 1)
// ---------------------------------------------------------------------------
__global__ void finalize(float4* __restrict__ out_ent) {
    int i = blockIdx.x * blockDim.x + threadIdx.x;
    if (i < N_ENT * C / 4) {
        int row = i >> 4;                      // C/4 = 16 float4 per row
        int   cnt = g_cnt[row];
        float inv = 1.0f / (float)(cnt > 1 ? cnt : 1);
        float4 v = out_ent[i];
        v.x *= inv; v.y *= inv; v.z *= inv; v.w *= inv;
        out_ent[i] = v;
    }
}

// ---------------------------------------------------------------------------
extern "C" void kernel_launch(void* const* d_in, const int* in_sizes, int n_in,
                              void* d_out, int out_size) {
    const float* entity_emb = (const float*)d_in[0];
    // d_in[1] = user_emb (unused by the reference outputs)
    const int*   edge_index = (const int*)d_in[2];
    const int*   edge_type  = (const int*)d_in[3];
    const int*   irows      = (const int*)d_in[4];
    const int*   icols      = (const int*)d_in[5];
    const float* ivals      = (const float*)d_in[6];
    const float* rwm        = (const float*)d_in[7];
    const float* weight     = (const float*)d_in[8];

    float* out_ent = (float*)d_out;                 // [N_ENT, C]
    float* out_usr = (float*)d_out + N_ENT * C;     // [N_USR, C]

    // 1. blend all entity rows
    {
        int n = N_ENT * C / 4;
        ent_init<<<(n + 255) / 256, 256>>>((const float4*)entity_emb);
    }
    // 2. region GEMM + blend (overwrites region rows of g_ent)
    region_gemm<<<(RD + GMT - 1) / GMT, 256>>>(entity_emb, rwm);
    // 3. zero sums + counts
    {
        int n = (N_ENT + N_USR) * C / 4;
        zero_all<<<(n + 255) / 256, 256>>>((float4*)d_out);
    }
    // 4. KG scatter
    {
        long long threads = (long long)N_EDGES * 16;
        int blocks = (int)((threads + 255) / 256);
        kg_agg<<<blocks, 256>>>(edge_index, edge_type, weight, out_ent);
    }
    // 5. user scatter
    {
        long long threads = (long long)NNZ * 16;
        int blocks = (int)((threads + 255) / 256);
        user_agg<<<blocks, 256>>>(irows, icols, ivals, out_usr);
    }
    // 6. divide by counts
    {
        int n = N_ENT * C / 4;
        finalize<<<(n + 255) / 256, 256>>>((float4*)out_ent);
    }
}

// round 2
// speedup vs baseline: 2.0913x; 2.0913x over previous
#include <cuda_runtime.h>

// Aggregator_9964324127508 — GB300 sm_103a, round 2
//
// Launch order (single stream, graph-capturable, no allocations):
//   1. prep         : g_ent = 0.8e+0.2e (all rows); zero d_out, g_cnt, g_region
//   2. region_gemm  : K-split register-tiled GEMM, red.v4 partials -> g_region
//   3. region_blend : g_ent[R0:R1] = 0.8*emb + 0.2*g_region
//   4. kg_agg       : 4 edges / 16-lane group, MLP-8 gathers, red.v4 scatter
//   5. user_agg     : 4 nnz / 16-lane group, same structure
//   6. finalize     : entity sums /= max(count,1)

#define N_ENT   100000
#define N_USR   50000
#define C       64
#define N_EDGES 1600000
#define NNZ     1000000
#define N_REL   32
#define R0      42033
#define RD      2597      // R1 - R0

__device__ float g_ent[N_ENT * C];     // blended entity embedding (~25.6 MB)
__device__ int   g_cnt[N_ENT];         // per-head edge counts
__device__ float g_region[RD * C];     // region GEMM partial accumulator

// ---------------------------------------------------------------------------
// 1. prep: blend all entity rows, zero outputs / counts / region scratch
// ---------------------------------------------------------------------------
__global__ void prep(const float4* __restrict__ emb, float4* __restrict__ out) {
    int i = blockIdx.x * blockDim.x + threadIdx.x;
    const float4 z = make_float4(0.f, 0.f, 0.f, 0.f);
    if (i < (N_ENT + N_USR) * C / 4) out[i] = z;
    if (i < N_ENT * C / 4) {
        float4 e = emb[i];
        float4 r;
        r.x = e.x * 0.8f + e.x * 0.2f;
        r.y = e.y * 0.8f + e.y * 0.2f;
        r.z = e.z * 0.8f + e.z * 0.2f;
        r.w = e.w * 0.8f + e.w * 0.2f;
        reinterpret_cast<float4*>(g_ent)[i] = r;
    }
    if (i < RD * C / 4) reinterpret_cast<float4*>(g_region)[i] = z;
    if (i < N_ENT / 4)  reinterpret_cast<int4*>(g_cnt)[i] = make_int4(0, 0, 0, 0);
}

// ---------------------------------------------------------------------------
// 2. region GEMM: out[r,c] = sum_k RWM[r,k]*emb[R0+k,c]
//    Register-tiled: block = 64 rows x 64 cols, thread = 4 rows x 4 cols.
//    Grid = (ceil(RD/64), KSPLIT); partials red.v4'd into g_region.
// ---------------------------------------------------------------------------
#define RT     64
#define KT     16
#define KSPLIT 8
#define KCHUNK ((RD + KSPLIT - 1) / KSPLIT)   // 325

__global__ __launch_bounds__(256) void region_gemm(
        const float* __restrict__ emb, const float* __restrict__ rwm) {
    __shared__ float As[RT][KT + 1];
    __shared__ float Bs[KT][C];

    const int tid = threadIdx.x;
    const int tx  = tid & 15;          // col group (4 cols)
    const int ty  = tid >> 4;          // 0..15; thread rows = ty + 16*j
    const int row0 = blockIdx.x * RT;
    const int ks   = blockIdx.y * KCHUNK;
    const int ke   = min(ks + KCHUNK, RD);

    float4 acc[4];
    #pragma unroll
    for (int j = 0; j < 4; j++) acc[j] = make_float4(0.f, 0.f, 0.f, 0.f);

    for (int k0 = ks; k0 < ke; k0 += KT) {
        // A tile: 64x16, 4 elems/thread
        #pragma unroll
        for (int q = 0; q < 4; q++) {
            int idx = tid + 256 * q;            // 0..1023
            int r = idx >> 4, k = idx & 15;
            int gr = row0 + r, gk = k0 + k;
            As[r][k] = (gr < RD && gk < ke) ? rwm[(long long)gr * RD + gk] : 0.f;
        }
        // B tile: 16x64, one float4/thread
        {
            int k = tid >> 4, c4 = tid & 15;
            int gk = k0 + k;
            float4 b = make_float4(0.f, 0.f, 0.f, 0.f);
            if (gk < ke)
                b = *reinterpret_cast<const float4*>(&emb[(R0 + gk) * C + c4 * 4]);
            *reinterpret_cast<float4*>(&Bs[k][c4 * 4]) = b;
        }
        __syncthreads();

        #pragma unroll
        for (int kk = 0; kk < KT; kk++) {
            float4 b = *reinterpret_cast<const float4*>(&Bs[kk][tx * 4]);
            #pragma unroll
            for (int j = 0; j < 4; j++) {
                float a = As[ty + 16 * j][kk];
                acc[j].x = fmaf(a, b.x, acc[j].x);
                acc[j].y = fmaf(a, b.y, acc[j].y);
                acc[j].z = fmaf(a, b.z, acc[j].z);
                acc[j].w = fmaf(a, b.w, acc[j].w);
            }
        }
        __syncthreads();
    }

    #pragma unroll
    for (int j = 0; j < 4; j++) {
        int row = row0 + ty + 16 * j;
        if (row < RD) {
            float* p = &g_region[row * C + tx * 4];
            asm volatile("red.global.add.v4.f32 [%0], {%1, %2, %3, %4};"
                         :: "l"(p), "f"(acc[j].x), "f"(acc[j].y),
                            "f"(acc[j].z), "f"(acc[j].w) : "memory");
        }
    }
}

// ---------------------------------------------------------------------------
// 3. region blend: g_ent[R0:R1] = 0.8*emb + 0.2*g_region
// ---------------------------------------------------------------------------
__global__ void region_blend(const float4* __restrict__ emb) {
    int i = blockIdx.x * blockDim.x + threadIdx.x;
    if (i < RD * C / 4) {
        float4 e = emb[R0 * C / 4 + i];
        float4 r = reinterpret_cast<const float4*>(g_region)[i];
        float4 o;
        o.x = e.x * 0.8f + r.x * 0.2f;
        o.y = e.y * 0.8f + r.y * 0.2f;
        o.z = e.z * 0.8f + r.z * 0.2f;
        o.w = e.w * 0.8f + r.w * 0.2f;
        reinterpret_cast<float4*>(g_ent)[R0 * C / 4 + i] = o;
    }
}

// ---------------------------------------------------------------------------
// 4. KG aggregate: 16 lanes x 4 edges per group. All 4 gathers + 4 weight
//    loads issued before the REDs (MLP 8), then 4 red.v4 scatters.
// ---------------------------------------------------------------------------
__global__ __launch_bounds__(256) void kg_agg(
        const int* __restrict__ eidx, const int* __restrict__ etype,
        const float* __restrict__ weight, float* __restrict__ out_ent) {
    long long t = (long long)blockIdx.x * blockDim.x + threadIdx.x;
    int p = (int)(t >> 4);                 // group of 4 edges
    if (p >= N_EDGES / 4) return;
    int lane = (int)(t & 15);
    int c = lane * 4;

    int4 h4 = reinterpret_cast<const int4*>(eidx)[p];
    int4 t4 = reinterpret_cast<const int4*>(eidx + N_EDGES)[p];
    int4 r4 = reinterpret_cast<const int4*>(etype)[p];
    int heads[4] = {h4.x, h4.y, h4.z, h4.w};
    int tails[4] = {t4.x, t4.y, t4.z, t4.w};
    int rels[4]  = {r4.x, r4.y, r4.z, r4.w};

    float4 x[4], w[4];
    #pragma unroll
    for (int j = 0; j < 4; j++)
        x[j] = *reinterpret_cast<const float4*>(&g_ent[tails[j] * C + c]);
    #pragma unroll
    for (int j = 0; j < 4; j++) {
        int rt = (rels[j] + (N_REL - 1)) & (N_REL - 1);
        w[j] = *reinterpret_cast<const float4*>(&weight[rt * C + c]);
    }
    #pragma unroll
    for (int j = 0; j < 4; j++) {
        float4 v;
        v.x = x[j].x * w[j].x; v.y = x[j].y * w[j].y;
        v.z = x[j].z * w[j].z; v.w = x[j].w * w[j].w;
        float* pdst = &out_ent[heads[j] * C + c];
        asm volatile("red.global.add.v4.f32 [%0], {%1, %2, %3, %4};"
                     :: "l"(pdst), "f"(v.x), "f"(v.y), "f"(v.z), "f"(v.w)
                     : "memory");
    }
    if (lane == 0) {
        #pragma unroll
        for (int j = 0; j < 4; j++) atomicAdd(&g_cnt[heads[j]], 1);
    }
}

// ---------------------------------------------------------------------------
// 5. user aggregate: 16 lanes x 4 nnz per group
// ---------------------------------------------------------------------------
__global__ __launch_bounds__(256) void user_agg(
        const int* __restrict__ rows, const int* __restrict__ cols,
        const float* __restrict__ vals, float* __restrict__ out_usr) {
    long long t = (long long)blockIdx.x * blockDim.x + threadIdx.x;
    int p = (int)(t >> 4);
    if (p >= NNZ / 4) return;
    int lane = (int)(t & 15);
    int c = lane * 4;

    int4   r4 = reinterpret_cast<const int4*>(rows)[p];
    int4   c4 = reinterpret_cast<const int4*>(cols)[p];
    float4 v4 = reinterpret_cast<const float4*>(vals)[p];
    int rr[4] = {r4.x, r4.y, r4.z, r4.w};
    int cc[4] = {c4.x, c4.y, c4.z, c4.w};
    float vv[4] = {v4.x, v4.y, v4.z, v4.w};

    float4 x[4];
    #pragma unroll
    for (int j = 0; j < 4; j++)
        x[j] = *reinterpret_cast<const float4*>(&g_ent[cc[j] * C + c]);
    #pragma unroll
    for (int j = 0; j < 4; j++) {
        float4 v;
        v.x = x[j].x * vv[j]; v.y = x[j].y * vv[j];
        v.z = x[j].z * vv[j]; v.w = x[j].w * vv[j];
        float* pdst = &out_usr[rr[j] * C + c];
        asm volatile("red.global.add.v4.f32 [%0], {%1, %2, %3, %4};"
                     :: "l"(pdst), "f"(v.x), "f"(v.y), "f"(v.z), "f"(v.w)
                     : "memory");
    }
}

// ---------------------------------------------------------------------------
// 6. entity_agg = sums / max(count, 1)
// ---------------------------------------------------------------------------
__global__ void finalize(float4* __restrict__ out_ent) {
    int i = blockIdx.x * blockDim.x + threadIdx.x;
    if (i < N_ENT * C / 4) {
        int row = i >> 4;                 // 16 float4 per row
        int cnt = g_cnt[row];
        float inv = 1.0f / (float)(cnt > 1 ? cnt : 1);
        float4 v = out_ent[i];
        v.x *= inv; v.y *= inv; v.z *= inv; v.w *= inv;
        out_ent[i] = v;
    }
}

// ---------------------------------------------------------------------------
extern "C" void kernel_launch(void* const* d_in, const int* in_sizes, int n_in,
                              void* d_out, int out_size) {
    const float* entity_emb = (const float*)d_in[0];
    const int*   edge_index = (const int*)d_in[2];
    const int*   edge_type  = (const int*)d_in[3];
    const int*   irows      = (const int*)d_in[4];
    const int*   icols      = (const int*)d_in[5];
    const float* ivals      = (const float*)d_in[6];
    const float* rwm        = (const float*)d_in[7];
    const float* weight     = (const float*)d_in[8];

    float* out_ent = (float*)d_out;                 // [N_ENT, C]
    float* out_usr = (float*)d_out + N_ENT * C;     // [N_USR, C]

    {   // 1. prep
        int n = (N_ENT + N_USR) * C / 4;
        prep<<<(n + 255) / 256, 256>>>((const float4*)entity_emb, (float4*)d_out);
    }
    {   // 2. region GEMM (K-split)
        dim3 grid((RD + RT - 1) / RT, KSPLIT);
        region_gemm<<<grid, 256>>>(entity_emb, rwm);
    }
    {   // 3. region blend
        int n = RD * C / 4;
        region_blend<<<(n + 255) / 256, 256>>>((const float4*)entity_emb);
    }
    {   // 4. KG scatter (4 edges per 16-lane group)
        long long threads = (long long)(N_EDGES / 4) * 16;
        kg_agg<<<(int)((threads + 255) / 256), 256>>>(edge_index, edge_type,
                                                      weight, out_ent);
    }
    {   // 5. user scatter
        long long threads = (long long)(NNZ / 4) * 16;
        user_agg<<<(int)((threads + 255) / 256), 256>>>(irows, icols, ivals,
                                                        out_usr);
    }
    {   // 6. finalize
        int n = N_ENT * C / 4;
        finalize<<<(n + 255) / 256, 256>>>((float4*)out_ent);
    }
}